// round 10
// baseline (speedup 1.0000x reference)
#include <cuda_runtime.h>

// PoseNoiseTransform single-pass decoupled-lookback quaternion scan.
// q_dot staged in dynamic SMEM (inputs read from DRAM exactly once);
// lookback is per-thread (per-column flags, acquire/release), no block syncs.
//
//   q:     [TS, NS, 4] f32 unit quaternions (w,x,y,z)
//   noise: [TS-1, NS, 4] f32 uniform [0,1)
//   out:   [TS, NS, 4] f32
//
// out[0]   = q[0]
// q_dot[t] = (q[t+1] * conj(q[t])) * normalize((noise[t]-0.5)*[1,.05,.05,.05])
// out[i+1] = q_dot[i] * ... * q_dot[0] * q[0]

#define BLK 256
#define CHUNK 26          // dyn SMEM = 256*26*16 = 104 KB -> 2 CTAs/SM
#define NCH_MAX 96
#define NS_MAX 8192

// Scratch (device globals; no allocation allowed anywhere).
__device__ float4 g_agg[NCH_MAX * NS_MAX];   // per-chunk aggregate, per column
__device__ float4 g_inc[NCH_MAX * NS_MAX];   // per-chunk inclusive, per column
__device__ int    g_flag[NCH_MAX * NS_MAX];  // per-column: 0=none 1=agg 2=inclusive
__device__ unsigned int g_vid;

// Quaternion in float4: .x=w .y=x .z=y .w=z ; returns a*b (Hamilton)
__device__ __forceinline__ float4 qmul(float4 a, float4 b) {
    float aw = a.x, ax = a.y, ay = a.z, az = a.w;
    float bw = b.x, bx = b.y, by = b.z, bz = b.w;
    return make_float4(
        aw * bw - ax * bx - ay * by - az * bz,
        aw * bx + ax * bw + ay * bz - az * by,
        aw * by - ax * bz + ay * bw + az * bx,
        aw * bz + ax * by - ay * bx + az * bw);
}

__device__ __forceinline__ float4 qdot_step(float4 qnext, float4 qprev, float4 nz) {
    // rel = qnext * conj(qprev), conj signs folded
    float aw = qnext.x, ax = qnext.y, ay = qnext.z, az = qnext.w;
    float bw = qprev.x, bx = -qprev.y, by = -qprev.z, bz = -qprev.w;
    float4 rel = make_float4(
        aw * bw - ax * bx - ay * by - az * bz,
        aw * bx + ax * bw + ay * bz - az * by,
        aw * by - ax * bz + ay * bw + az * bx,
        aw * bz + ax * by - ay * bx + az * bw);

    // q_samp = normalize((nz - 0.5) * [1, .05, .05, .05])
    float sw = nz.x - 0.5f;
    float sx = (nz.y - 0.5f) * 0.05f;
    float sy = (nz.z - 0.5f) * 0.05f;
    float sz = (nz.w - 0.5f) * 0.05f;
    float d = sw * sw + sx * sx + sy * sy + sz * sz;
    float r = rsqrtf(d);
    r = r * (1.5f - 0.5f * d * r * r);   // Newton step -> full fp32 accuracy
    float4 samp = make_float4(sw * r, sx * r, sy * r, sz * r);

    return qmul(rel, samp);
}

__device__ __forceinline__ int ld_acquire(const int* p) {
    int v;
    asm volatile("ld.acquire.gpu.global.b32 %0, [%1];" : "=r"(v) : "l"(p) : "memory");
    return v;
}
__device__ __forceinline__ void st_release(int* p, int v) {
    asm volatile("st.release.gpu.global.b32 [%0], %1;" :: "l"(p), "r"(v) : "memory");
}

// Zero only the used flag region (nflag4 int4s), wide stores.
__global__ void init_kernel(int nflag4) {
    int i = blockIdx.x * blockDim.x + threadIdx.x;
    int4* f4 = reinterpret_cast<int4*>(g_flag);
    if (i < nflag4) f4[i] = make_int4(0, 0, 0, 0);
    if (i == 0) g_vid = 0u;
}

__global__ void __launch_bounds__(BLK) scan_kernel(
    const float4* __restrict__ q, const float4* __restrict__ noise,
    float4* __restrict__ out, int NS, int T, int CB, int NCH)
{
    extern __shared__ float4 sdot[];      // [CHUNK][BLK], each thread uses own column
    __shared__ unsigned int s_vid;

    // Dynamic block id: scheduling order == chunk order -> lookback safe.
    if (threadIdx.x == 0) s_vid = atomicAdd(&g_vid, 1u);
    __syncthreads();
    unsigned int vid = s_vid;
    int c  = (int)(vid / (unsigned)CB);
    int cb = (int)(vid % (unsigned)CB);
    int n  = cb * BLK + threadIdx.x;
    if (n >= NS) return;                  // no cross-thread deps -> safe to exit

    int t0 = c * CHUNK;
    int t1 = min(T, t0 + CHUNK);
    int len = t1 - t0;                    // 1..CHUNK

    // ---- Walk 1: compute q_dot -> SMEM (own column), accumulate aggregate A ----
    float4 A = make_float4(1.f, 0.f, 0.f, 0.f);
    {
        float4 qprev = q[(size_t)t0 * NS + n];
        #pragma unroll 4
        for (int i = 0; i < len; ++i) {
            int t = t0 + i;
            float4 qn = q[(size_t)(t + 1) * NS + n];
            float4 nz = noise[(size_t)t * NS + n];
            float4 qd = qdot_step(qn, qprev, nz);
            sdot[i * BLK + threadIdx.x] = qd;
            A = qmul(qd, A);
            qprev = qn;
        }
    }

    // ---- Per-thread decoupled lookback (per-column flags) ----
    float4 S = make_float4(1.f, 0.f, 0.f, 0.f);  // exclusive prefix P_{c-1}
    if (c > 0) {
        if (c < NCH - 1) {                        // last chunk's aggregate is never read
            g_agg[c * NS + n] = A;
            st_release(&g_flag[c * NS + n], 1);   // release orders payload
        }

        int p = c - 1;
        while (true) {
            int s;
            int backoff = 16;
            while ((s = ld_acquire(&g_flag[p * NS + n])) == 0) {
                __nanosleep(backoff);
                if (backoff < 256) backoff += backoff;
            }
            if (s >= 2) { S = qmul(S, g_inc[p * NS + n]); break; }
            S = qmul(S, g_agg[p * NS + n]);
            if (--p < 0) break;
        }
    }

    // ---- Publish inclusive P_c = A * P_{c-1} ----
    if (c < NCH - 1) {                    // last chunk's inclusive is never read
        float4 P = qmul(A, S);
        g_inc[c * NS + n] = P;
        st_release(&g_flag[c * NS + n], 2);
    }

    // ---- Walk 2: replay q_dot from SMEM (own column), write outputs ----
    float4 q0 = q[n];
    if (c == 0) out[n] = q0;              // out[0] = q[0]
    float4 acc = qmul(S, q0);             // carry = P_{c-1} * q[0]
    #pragma unroll 4
    for (int i = 0; i < len; ++i) {
        acc = qmul(sdot[i * BLK + threadIdx.x], acc);
        out[(size_t)(t0 + i + 1) * NS + n] = acc;
    }
}

extern "C" void kernel_launch(void* const* d_in, const int* in_sizes, int n_in,
                              void* d_out, int out_size)
{
    const float4* q     = (const float4*)d_in[0];
    const float4* noise = (const float4*)d_in[1];
    float4* out         = (float4*)d_out;

    int quats0 = in_sizes[0] / 4;          // TS*NS
    int quats1 = in_sizes[1] / 4;          // (TS-1)*NS
    int NS = quats0 - quats1;
    int TS = quats0 / NS;
    int T  = TS - 1;
    int nch = (T + CHUNK - 1) / CHUNK;     // chunks (<= NCH_MAX)
    int CB  = (NS + BLK - 1) / BLK;        // column-blocks

    int smem_bytes = CHUNK * BLK * (int)sizeof(float4);   // 104 KB
    static int attr_set = 0;
    if (!attr_set) {
        cudaFuncSetAttribute(scan_kernel,
                             cudaFuncAttributeMaxDynamicSharedMemorySize, smem_bytes);
        attr_set = 1;
    }

    int nflags = nch * NS;                 // used flag words
    int nflag4 = (nflags + 3) / 4;         // int4 count (arrays are 16B-aligned, padded)
    init_kernel<<<(nflag4 + 255) / 256, 256>>>(nflag4);
    scan_kernel<<<nch * CB, BLK, smem_bytes>>>(q, noise, out, NS, T, CB, nch);
}

// round 11
// speedup vs baseline: 1.2718x; 1.2718x over previous
#include <cuda_runtime.h>

// PoseNoiseTransform single-pass decoupled-lookback quaternion scan.
// Local running prefixes staged in SMEM (inputs read from DRAM exactly once);
// lookback is per-thread (per-column flags, acquire/release), no block syncs.
//
//   q:     [TS, NS, 4] f32 unit quaternions (w,x,y,z)
//   noise: [TS-1, NS, 4] f32 uniform [0,1)
//   out:   [TS, NS, 4] f32
//
// out[0]   = q[0]
// q_dot[t] = (q[t+1] * conj(q[t])) * normalize((noise[t]-0.5)*[1,.05,.05,.05])
// out[i+1] = q_dot[i] * ... * q_dot[0] * q[0]

#define BLK 256
#define CHUNK 11          // SMEM = 256*11*16 = 45056 B -> 5 CTAs/SM (proven best)
#define NCH_MAX 192
#define NS_MAX 8192

// Scratch (device globals; no allocation allowed anywhere).
__device__ float4 g_agg[NCH_MAX * NS_MAX];   // per-chunk aggregate, per column
__device__ float4 g_inc[NCH_MAX * NS_MAX];   // per-chunk inclusive, per column
__device__ int    g_flag[NCH_MAX * NS_MAX];  // per-column: 0=none 1=agg 2=inclusive
__device__ unsigned int g_vid;

// Quaternion in float4: .x=w .y=x .z=y .w=z ; returns a*b (Hamilton)
__device__ __forceinline__ float4 qmul(float4 a, float4 b) {
    float aw = a.x, ax = a.y, ay = a.z, az = a.w;
    float bw = b.x, bx = b.y, by = b.z, bz = b.w;
    return make_float4(
        aw * bw - ax * bx - ay * by - az * bz,
        aw * bx + ax * bw + ay * bz - az * by,
        aw * by - ax * bz + ay * bw + az * bx,
        aw * bz + ax * by - ay * bx + az * bw);
}

__device__ __forceinline__ float4 qdot_step(float4 qnext, float4 qprev, float4 nz) {
    // rel = qnext * conj(qprev), conj signs folded
    float aw = qnext.x, ax = qnext.y, ay = qnext.z, az = qnext.w;
    float bw = qprev.x, bx = -qprev.y, by = -qprev.z, bz = -qprev.w;
    float4 rel = make_float4(
        aw * bw - ax * bx - ay * by - az * bz,
        aw * bx + ax * bw + ay * bz - az * by,
        aw * by - ax * bz + ay * bw + az * bx,
        aw * bz + ax * by - ay * bx + az * bw);

    // q_samp = normalize((nz - 0.5) * [1, .05, .05, .05])
    float sw = nz.x - 0.5f;
    float sx = (nz.y - 0.5f) * 0.05f;
    float sy = (nz.z - 0.5f) * 0.05f;
    float sz = (nz.w - 0.5f) * 0.05f;
    float d = sw * sw + sx * sx + sy * sy + sz * sz;
    float r = rsqrtf(d);
    r = r * (1.5f - 0.5f * d * r * r);   // Newton step -> full fp32 accuracy
    float4 samp = make_float4(sw * r, sx * r, sy * r, sz * r);

    return qmul(rel, samp);
}

__device__ __forceinline__ int ld_acquire(const int* p) {
    int v;
    asm volatile("ld.acquire.gpu.global.b32 %0, [%1];" : "=r"(v) : "l"(p) : "memory");
    return v;
}
__device__ __forceinline__ void st_release(int* p, int v) {
    asm volatile("st.release.gpu.global.b32 [%0], %1;" :: "l"(p), "r"(v) : "memory");
}

// Zero only the used flag region (nflag4 int4s), wide stores.
__global__ void init_kernel(int nflag4) {
    int i = blockIdx.x * blockDim.x + threadIdx.x;
    int4* f4 = reinterpret_cast<int4*>(g_flag);
    if (i < nflag4) f4[i] = make_int4(0, 0, 0, 0);
    if (i == 0) g_vid = 0u;
}

__global__ void __launch_bounds__(BLK) scan_kernel(
    const float4* __restrict__ q, const float4* __restrict__ noise,
    float4* __restrict__ out, int NS, int T, int CB, int NCH)
{
    __shared__ float4 spre[CHUNK][BLK];   // running LOCAL prefixes (own column only)
    __shared__ unsigned int s_vid;

    // Dynamic block id: scheduling order == chunk order -> lookback safe.
    if (threadIdx.x == 0) s_vid = atomicAdd(&g_vid, 1u);
    __syncthreads();
    unsigned int vid = s_vid;
    int c  = (int)(vid / (unsigned)CB);
    int cb = (int)(vid % (unsigned)CB);
    int n  = cb * BLK + threadIdx.x;
    if (n >= NS) return;                  // no cross-thread deps -> safe to exit

    int t0 = c * CHUNK;
    int t1 = min(T, t0 + CHUNK);
    int len = t1 - t0;                    // 1..CHUNK

    // ---- Walk 1: running local prefix -> SMEM; A ends as chunk aggregate ----
    float4 A = make_float4(1.f, 0.f, 0.f, 0.f);
    {
        float4 qprev = q[(size_t)t0 * NS + n];
        #pragma unroll
        for (int i = 0; i < CHUNK; ++i) {
            if (i < len) {
                int t = t0 + i;
                float4 qn = q[(size_t)(t + 1) * NS + n];
                float4 nz = noise[(size_t)t * NS + n];
                float4 qd = qdot_step(qn, qprev, nz);
                A = qmul(qd, A);                  // local prefix qdot[i]*...*qdot[t0]
                spre[i][threadIdx.x] = A;
                qprev = qn;
            }
        }
    }

    // ---- Per-thread decoupled lookback (per-column flags) ----
    float4 S = make_float4(1.f, 0.f, 0.f, 0.f);  // exclusive prefix P_{c-1}
    if (c > 0) {
        if (c < NCH - 1) {                        // last chunk's agg is never read
            g_agg[c * NS + n] = A;
            st_release(&g_flag[c * NS + n], 1);   // release orders payload
        }

        int p = c - 1;
        while (true) {
            int s;
            int backoff = 16;
            while ((s = ld_acquire(&g_flag[p * NS + n])) == 0) {
                __nanosleep(backoff);
                if (backoff < 256) backoff += backoff;
            }
            if (s >= 2) { S = qmul(S, g_inc[p * NS + n]); break; }
            S = qmul(S, g_agg[p * NS + n]);
            if (--p < 0) break;
        }
    }

    // ---- Publish inclusive P_c = A * P_{c-1} ----
    if (c < NCH - 1) {                    // last chunk's inclusive is never read
        float4 P = qmul(A, S);
        g_inc[c * NS + n] = P;
        st_release(&g_flag[c * NS + n], 2);
    }

    // ---- Walk 2: out = local_prefix[i] * carry; fully independent per i ----
    float4 q0 = q[n];
    if (c == 0) out[n] = q0;              // out[0] = q[0]
    float4 carry = qmul(S, q0);           // P_{c-1} * q[0]
    #pragma unroll
    for (int i = 0; i < CHUNK; ++i) {
        if (i < len) {
            out[(size_t)(t0 + i + 1) * NS + n] = qmul(spre[i][threadIdx.x], carry);
        }
    }
}

extern "C" void kernel_launch(void* const* d_in, const int* in_sizes, int n_in,
                              void* d_out, int out_size)
{
    const float4* q     = (const float4*)d_in[0];
    const float4* noise = (const float4*)d_in[1];
    float4* out         = (float4*)d_out;

    int quats0 = in_sizes[0] / 4;          // TS*NS
    int quats1 = in_sizes[1] / 4;          // (TS-1)*NS
    int NS = quats0 - quats1;
    int TS = quats0 / NS;
    int T  = TS - 1;
    int nch = (T + CHUNK - 1) / CHUNK;     // chunks (<= NCH_MAX)
    int CB  = (NS + BLK - 1) / BLK;        // column-blocks

    int nflags = nch * NS;                 // used flag words
    int nflag4 = (nflags + 3) / 4;         // int4 count (array is 16B-aligned, padded)
    init_kernel<<<(nflag4 + 255) / 256, 256>>>(nflag4);
    scan_kernel<<<nch * CB, BLK>>>(q, noise, out, NS, T, CB, nch);
}